// round 15
// baseline (speedup 1.0000x reference)
#include <cuda_runtime.h>
#include <cuda_bf16.h>
#include <cstdint>
#include <cstddef>

// Problem constants
#define BB   256     // batch
#define SS   512     // seq len
#define VV   50000   // vocab
#define EE   300     // embed dim
#define HH   128     // hidden
#define NG   1024    // 2 dirs * 4H gate columns

#define VROWS 50048  // VV padded to 128
#define KP0   320    // EE padded to 32
#define KP1   256    // 2H (already /32)

// ---------------------------------------------------------------------------
// Scratch (static device globals — no runtime allocation allowed)
// ---------------------------------------------------------------------------
__device__ __align__(16) float g_P  [(size_t)VV * NG];          // projected vocab table (+b0)
__device__ __align__(16) __nv_bfloat16 g_h0h[(size_t)SS * BB * 256]; // layer-0 h, bf16 hi
__device__ __align__(16) __nv_bfloat16 g_h0l[(size_t)SS * BB * 256]; // layer-0 h, bf16 lo
__device__ __align__(16) float g_gx1[(size_t)SS * BB * NG];     // layer-1 input proj (+b1)
__device__ __align__(16) float g_hT [(size_t)BB * 256];         // layer-1 final hidden
// pre-split bf16 hi/lo operands (zero-padded) for the GEMMs
__device__ __align__(16) __nv_bfloat16 g_embh[(size_t)VROWS * KP0];
__device__ __align__(16) __nv_bfloat16 g_embl[(size_t)VROWS * KP0];
__device__ __align__(16) __nv_bfloat16 g_w0h [(size_t)NG * KP0];
__device__ __align__(16) __nv_bfloat16 g_w0l [(size_t)NG * KP0];
__device__ __align__(16) __nv_bfloat16 g_w1h [(size_t)NG * KP1];
__device__ __align__(16) __nv_bfloat16 g_w1l [(size_t)NG * KP1];

// ---------------------------------------------------------------------------
// Helpers
// ---------------------------------------------------------------------------
__device__ __forceinline__ uint32_t smem_u32(const void* p) {
    uint32_t a;
    asm("{ .reg .u64 t; cvta.to.shared.u64 t, %1; cvt.u32.u64 %0, t; }"
        : "=r"(a) : "l"(p));
    return a;
}
__device__ __forceinline__ void ffma2(unsigned long long& c,
                                      unsigned long long a,
                                      unsigned long long b) {
    asm("fma.rn.f32x2 %0, %1, %2, %0;" : "+l"(c) : "l"(a), "l"(b));
}
__device__ __forceinline__ float2 unpk2(unsigned long long v) {
    float2 f;
    asm("mov.b64 {%0, %1}, %2;" : "=f"(f.x), "=f"(f.y) : "l"(v));
    return f;
}
__device__ __forceinline__ float sigm_f(float x) {
    return 1.0f / (1.0f + __expf(-x));
}
__device__ __forceinline__ float tanh_f(float x) {
    float a = fabsf(x);
    float t = __expf(-2.0f * a);
    float r = (1.0f - t) / (1.0f + t);
    return copysignf(r, x);
}

// ldmatrix x4 (b16) — baseline PTX, legal on compute_103
__device__ __forceinline__ void ldm4(uint32_t& r0, uint32_t& r1,
                                     uint32_t& r2, uint32_t& r3, uint32_t addr) {
    asm volatile("ldmatrix.sync.aligned.m8n8.x4.shared.b16 {%0,%1,%2,%3}, [%4];"
                 : "=r"(r0), "=r"(r1), "=r"(r2), "=r"(r3) : "r"(addr));
}
// mma m16n8k16 bf16 -> f32 accumulate — baseline PTX (sm_80+)
__device__ __forceinline__ void mma16816(float* d, const uint32_t* a,
                                         uint32_t b0, uint32_t b1) {
    asm volatile(
        "mma.sync.aligned.m16n8k16.row.col.f32.bf16.bf16.f32 "
        "{%0,%1,%2,%3}, {%4,%5,%6,%7}, {%8,%9}, {%0,%1,%2,%3};"
        : "+f"(d[0]), "+f"(d[1]), "+f"(d[2]), "+f"(d[3])
        : "r"(a[0]), "r"(a[1]), "r"(a[2]), "r"(a[3]), "r"(b0), "r"(b1));
}
// cp.async 16B — baseline PTX (sm_80+)
__device__ __forceinline__ void cpa16(uint32_t dst, const void* src) {
    asm volatile("cp.async.cg.shared.global [%0], [%1], 16;" :: "r"(dst), "l"(src));
}
__device__ __forceinline__ void cp_commit() {
    asm volatile("cp.async.commit_group;" ::: "memory");
}
__device__ __forceinline__ void cp_wait0() {
    asm volatile("cp.async.wait_group 0;" ::: "memory");
}

// ---------------------------------------------------------------------------
// Presplit: fp32 [rows_src, K] -> bf16 hi/lo [*, KP] zero-padded.
// hi = rn(v), lo = rn(v - hi): identical numerics to the inline split.
// ---------------------------------------------------------------------------
template<int DST>   // 0: emb (KP0); 1: w_ih0 (KP0); 2: w_ih1 (KP1)
__global__ __launch_bounds__(256)
void presplit(const float* __restrict__ src, int rows_src, int K, int n4)
{
    __nv_bfloat16* dh = (DST == 0) ? g_embh : (DST == 1) ? g_w0h : g_w1h;
    __nv_bfloat16* dl = (DST == 0) ? g_embl : (DST == 1) ? g_w0l : g_w1l;
    const int KP = (DST == 2) ? KP1 : KP0;

    int idx = blockIdx.x * 256 + threadIdx.x;
    if (idx >= n4) return;
    int row = idx / (KP >> 2);
    int c   = (idx - row * (KP >> 2)) << 2;

    float4 v = make_float4(0.f, 0.f, 0.f, 0.f);
    if (row < rows_src && c + 3 < K)
        v = *reinterpret_cast<const float4*>(&src[(size_t)row * K + c]);

    __nv_bfloat16 hx = __float2bfloat16(v.x), hy = __float2bfloat16(v.y);
    __nv_bfloat16 hz = __float2bfloat16(v.z), hw = __float2bfloat16(v.w);
    __nv_bfloat16 lx = __float2bfloat16(v.x - __bfloat162float(hx));
    __nv_bfloat16 ly = __float2bfloat16(v.y - __bfloat162float(hy));
    __nv_bfloat16 lz = __float2bfloat16(v.z - __bfloat162float(hz));
    __nv_bfloat16 lw = __float2bfloat16(v.w - __bfloat162float(hw));

    union { __nv_bfloat162 h[2]; uint2 u; } t;
    t.h[0] = __halves2bfloat162(hx, hy); t.h[1] = __halves2bfloat162(hz, hw);
    *reinterpret_cast<uint2*>(&dh[(size_t)row * KP + c]) = t.u;
    t.h[0] = __halves2bfloat162(lx, ly); t.h[1] = __halves2bfloat162(lz, lw);
    *reinterpret_cast<uint2*>(&dl[(size_t)row * KP + c]) = t.u;
}

// ---------------------------------------------------------------------------
// Tensor-core GEMM, split-bf16 fp32 emulation (acc += AhBh + AhBl + AlBh).
// ROUND-14 FIX: warp-skewed ks order — even warps process k16 steps (0,1),
// odd warps (1,0). Breaks the post-barrier phase-lock so half the warps are
// in their ldmatrix phase while the other half are in their mma phase:
// crossbar and tensor pipes overlap instead of alternating storms.
// (Only per-accumulator k-chunk order changes for odd warps — fp32
// reassociation well inside the 1e-3 tolerance; measured margin is 1000x.)
// BM=128, BN=128, BK=32, 256 threads = 8 warps (4m x 2n), warp tile 32x64.
// ---------------------------------------------------------------------------
#define GEMM_DSM 81920   // 2 * 40960 bytes

template<int WHICH>
__global__ __launch_bounds__(256, 2)
void gemm_cp(const float* __restrict__ bias, int M)
{
    extern __shared__ __align__(16) char dsm[];

    const __nv_bfloat16* __restrict__ Ah_ = (WHICH == 0) ? g_embh : g_h0h;
    const __nv_bfloat16* __restrict__ Al_ = (WHICH == 0) ? g_embl : g_h0l;
    const __nv_bfloat16* __restrict__ Bh_ = (WHICH == 0) ? g_w0h  : g_w1h;
    const __nv_bfloat16* __restrict__ Bl_ = (WHICH == 0) ? g_w0l  : g_w1l;
    float* __restrict__ C = (WHICH == 0) ? g_P : g_gx1;
    constexpr int KP  = (WHICH == 0) ? KP0 : KP1;
    constexpr int nKT = KP / 32;

    const int tid  = threadIdx.x;
    const int wid  = tid >> 5;
    const int lane = tid & 31;
    const int wm   = wid & 3;
    const int wn   = wid >> 2;
    const int kskew = wid & 1;      // ks traversal order per warp

    const int mTile = blockIdx.y * 128;
    const int nTile = blockIdx.x * 128;
    const uint32_t sb = smem_u32(dsm);

    // fill geometry: thread -> row fr, 2x16B at col half fc
    const int fr = tid >> 1;
    const int fc = (tid & 1) * 16;                 // bf16 elems
    const __nv_bfloat16* sAh = Ah_ + (size_t)(mTile + fr) * KP + fc;
    const __nv_bfloat16* sAl = Al_ + (size_t)(mTile + fr) * KP + fc;
    const __nv_bfloat16* sBh = Bh_ + (size_t)(nTile + fr) * KP + fc;
    const __nv_bfloat16* sBl = Bl_ + (size_t)(nTile + fr) * KP + fc;
    const uint32_t dstb = (uint32_t)(fr * 80 + fc * 2);   // bytes in matrix region

    // ldmatrix lane geometry (m16n8k16 fragments)
    const int a_row = ((lane >> 3) & 1) * 8 + (lane & 7);
    const int a_k   = (lane >> 4) * 8;
    const int b_row = (lane >> 4) * 8 + (lane & 7);
    const int b_k   = ((lane >> 3) & 1) * 8;

    float acc[2][8][4];
    #pragma unroll
    for (int i = 0; i < 2; i++)
        #pragma unroll
        for (int j = 0; j < 8; j++)
            #pragma unroll
            for (int q = 0; q < 4; q++) acc[i][j][q] = 0.0f;

    // prologue: tile 0 -> buffer 0
    {
        const uint32_t d = sb + dstb;
        cpa16(d,             sAh);  cpa16(d + 16,         sAh + 8);
        cpa16(d + 10240,     sAl);  cpa16(d + 10240 + 16, sAl + 8);
        cpa16(d + 20480,     sBh);  cpa16(d + 20480 + 16, sBh + 8);
        cpa16(d + 30720,     sBl);  cpa16(d + 30720 + 16, sBl + 8);
        cp_commit();
    }

    for (int kt = 0; kt < nKT; kt++) {
        cp_wait0();          // tile kt landed (only group pending)
        __syncthreads();     // all warps: kt visible; compute(kt-1) complete

        // issue next tile AFTER the barrier -> overlaps with compute below
        if (kt + 1 < nKT) {
            const uint32_t d = sb + (uint32_t)(((kt + 1) & 1) * 40960) + dstb;
            const int ko = (kt + 1) * 32;
            cpa16(d,             sAh + ko);  cpa16(d + 16,         sAh + ko + 8);
            cpa16(d + 10240,     sAl + ko);  cpa16(d + 10240 + 16, sAl + ko + 8);
            cpa16(d + 20480,     sBh + ko);  cpa16(d + 20480 + 16, sBh + ko + 8);
            cpa16(d + 30720,     sBl + ko);  cpa16(d + 30720 + 16, sBl + ko + 8);
            cp_commit();
        }

        const uint32_t uAh = sb + (uint32_t)((kt & 1) * 40960);
        const uint32_t uAl = uAh + 10240;
        const uint32_t uBh = uAh + 20480;
        const uint32_t uBl = uAh + 30720;

        #pragma unroll
        for (int ksx = 0; ksx < 2; ksx++) {
            const int ks = ksx ^ kskew;   // warp-skewed traversal
            uint32_t ah[2][4], al[2][4];
            #pragma unroll
            for (int mt = 0; mt < 2; mt++) {
                const uint32_t off =
                    (uint32_t)(((wm * 32 + mt * 16 + a_row) * 40 + ks * 16 + a_k) * 2);
                ldm4(ah[mt][0], ah[mt][1], ah[mt][2], ah[mt][3], uAh + off);
                ldm4(al[mt][0], al[mt][1], al[mt][2], al[mt][3], uAl + off);
            }
            #pragma unroll
            for (int np = 0; np < 4; np++) {
                const uint32_t off =
                    (uint32_t)(((wn * 64 + np * 16 + b_row) * 40 + ks * 16 + b_k) * 2);
                uint32_t bh[4], bl[4];
                ldm4(bh[0], bh[1], bh[2], bh[3], uBh + off);
                ldm4(bl[0], bl[1], bl[2], bl[3], uBl + off);
                float* d00 = acc[0][np * 2 + 0];
                float* d10 = acc[1][np * 2 + 0];
                float* d01 = acc[0][np * 2 + 1];
                float* d11 = acc[1][np * 2 + 1];
                // pass 0: Ah x Bh
                mma16816(d00, ah[0], bh[0], bh[1]);
                mma16816(d10, ah[1], bh[0], bh[1]);
                mma16816(d01, ah[0], bh[2], bh[3]);
                mma16816(d11, ah[1], bh[2], bh[3]);
                // pass 1: Ah x Bl
                mma16816(d00, ah[0], bl[0], bl[1]);
                mma16816(d10, ah[1], bl[0], bl[1]);
                mma16816(d01, ah[0], bl[2], bl[3]);
                mma16816(d11, ah[1], bl[2], bl[3]);
                // pass 2: Al x Bh
                mma16816(d00, al[0], bh[0], bh[1]);
                mma16816(d10, al[1], bh[0], bh[1]);
                mma16816(d01, al[0], bh[2], bh[3]);
                mma16816(d11, al[1], bh[2], bh[3]);
            }
        }
    }

    // ---- epilogue: c-frag rows lane>>2 (+8), cols (lane&3)*2; guard M
    const int lrow = lane >> 2;
    const int lcol = (lane & 3) * 2;
    #pragma unroll
    for (int mt = 0; mt < 2; mt++) {
        const int gm0 = mTile + wm * 32 + mt * 16 + lrow;
        #pragma unroll
        for (int nt = 0; nt < 8; nt++) {
            const int gn0 = nTile + wn * 64 + nt * 8 + lcol;
            const float bz0 = bias[gn0], bz1 = bias[gn0 + 1];
            if (gm0 < M) {
                float2 v = make_float2(acc[mt][nt][0] + bz0, acc[mt][nt][1] + bz1);
                *reinterpret_cast<float2*>(&C[(size_t)gm0 * NG + gn0]) = v;
            }
            if (gm0 + 8 < M) {
                float2 v = make_float2(acc[mt][nt][2] + bz0, acc[mt][nt][3] + bz1);
                *reinterpret_cast<float2*>(&C[(size_t)(gm0 + 8) * NG + gn0]) = v;
            }
        }
    }
}

// ---------------------------------------------------------------------------
// Recurrence v5 (measured best — UNCHANGED).
// G=2 gates per thread, k-split 2; g0 w-half in regs, g1 w-half in smem slots;
// h_sm 72-float half-pitch; kh-pair shfl_xor(1); transposed z_sm[b][520];
// gx prefetched one step ahead.
// LAYER==0 emits h as bf16 hi/lo (pre-split for GEMM1's A operand).
// ---------------------------------------------------------------------------
#define REC_SMEM_BYTES ((32768 + 576 + 2080) * 4 + 2048 * 4)

template<int LAYER>
__global__ __launch_bounds__(512, 1)
void recur_kernel(const int* __restrict__ tokens,
                  const float* __restrict__ w_hh)   // [2,512,128]
{
    extern __shared__ __align__(16) float smem[];
    float* w_sm   = smem;                    // slot layout, 32768 floats
    float* h_sm   = smem + 32768;            // [4 b][2 kh x 72]
    float* z_sm   = h_sm + 576;              // [4 b][520]
    int*   tok_sm = (int*)(z_sm + 2080);     // [4][512]

    const int tid   = threadIdx.x;
    const int chunk = blockIdx.x;
    const int dir   = blockIdx.y;
    const int gp    = tid >> 1;
    const int kh    = tid & 1;
    const int warp  = tid >> 5;
    const int lane  = tid & 31;

    unsigned long long wr2[32];
    {
        const unsigned long long* wp = reinterpret_cast<const unsigned long long*>(
            &w_hh[((size_t)dir * 512 + 2 * gp) * 128 + kh * 64]);
        #pragma unroll
        for (int i = 0; i < 32; i++) wr2[i] = wp[i];
    }
    {
        const float* wsrc = &w_hh[((size_t)dir * 512 + 2 * gp + 1) * 128 + kh * 64];
        float* wdst = &w_sm[(size_t)(warp * 16 * 32 + lane) * 4];
        #pragma unroll
        for (int t = 0; t < 16; t++)
            *reinterpret_cast<float4*>(&wdst[t * 128]) =
                *reinterpret_cast<const float4*>(&wsrc[t * 4]);
    }
    if (LAYER == 0) {
        for (int idx = tid; idx < 4 * 512; idx += 512)
            tok_sm[idx] = tokens[(size_t)(chunk * 4 + (idx >> 9)) * SS + (idx & 511)];
    }
    for (int idx = tid; idx < 576; idx += 512) h_sm[idx] = 0.0f;
    __syncthreads();

    const int jj = tid & 127;
    const int bb = tid >> 7;
    const int col = dir * 512 + tid;
    const float* __restrict__ gsrc = (LAYER == 0) ? g_P : g_gx1;
    const float* wslot = &w_sm[(size_t)(warp * 16 * 32 + lane) * 4];
    float c_st = 0.0f, h_last = 0.0f;

    // prologue: gx for step 0
    float gxv[4];
    {
        const int s0 = dir ? 511 : 0;
        #pragma unroll
        for (int b = 0; b < 4; b++) {
            size_t row = (LAYER == 0)
                ? (size_t)tok_sm[b * 512 + s0]
                : ((size_t)s0 * BB + (chunk * 4 + b));
            gxv[b] = gsrc[row * NG + col];
        }
    }

    for (int si = 0; si < 512; si++) {
        const int s = dir ? (511 - si) : si;

        // --- prefetch gx for step si+1 (consumed next iter; DRAM hidden)
        float gxn[4] = {0.f, 0.f, 0.f, 0.f};
        if (si < 511) {
            const int sn = dir ? (510 - si) : (si + 1);
            #pragma unroll
            for (int b = 0; b < 4; b++) {
                size_t row = (LAYER == 0)
                    ? (size_t)tok_sm[b * 512 + sn]
                    : ((size_t)sn * BB + (chunk * 4 + b));
                gxn[b] = gsrc[row * NG + col];
            }
        }

        unsigned long long accA[4] = {0ull, 0ull, 0ull, 0ull};
        unsigned long long accB[4] = {0ull, 0ull, 0ull, 0ull};
        #pragma unroll
        for (int t = 0; t < 16; t++) {
            ulonglong2 w2 = *reinterpret_cast<const ulonglong2*>(&wslot[t * 128]);
            #pragma unroll
            for (int b = 0; b < 4; b++) {
                ulonglong2 h2 = *reinterpret_cast<const ulonglong2*>(
                    &h_sm[b * 144 + kh * 72 + t * 4]);
                ffma2(accA[b], wr2[2 * t],     h2.x);
                ffma2(accA[b], wr2[2 * t + 1], h2.y);
                ffma2(accB[b], w2.x, h2.x);
                ffma2(accB[b], w2.y, h2.y);
            }
        }
        #pragma unroll
        for (int b = 0; b < 4; b++) {
            float2 fA = unpk2(accA[b]);
            float2 fB = unpk2(accB[b]);
            float sA = fA.x + fA.y;
            float sB = fB.x + fB.y;
            float send = kh ? sA : sB;
            float recv = __shfl_xor_sync(0xffffffffu, send, 1);
            float own  = kh ? sB : sA;
            z_sm[b * 520 + tid] = own + recv + gxv[b];
        }
        __syncthreads();

        {
            const float* zrow = &z_sm[bb * 520];
            float zi = zrow[      jj];
            float zf = zrow[128 + jj];
            float zg = zrow[256 + jj];
            float zo = zrow[384 + jj];
            float ig = sigm_f(zi), fg = sigm_f(zf), og = sigm_f(zo);
            float gv = tanh_f(zg);
            c_st = fg * c_st + ig * gv;
            float hh = og * tanh_f(c_st);
            h_last = hh;
            h_sm[bb * 144 + (jj >> 6) * 72 + (jj & 63)] = hh;
            if (LAYER == 0) {
                __nv_bfloat16 hi = __float2bfloat16(hh);
                __nv_bfloat16 lo = __float2bfloat16(hh - __bfloat162float(hi));
                const size_t off =
                    ((size_t)s * BB + (chunk * 4 + bb)) * 256 + dir * 128 + jj;
                g_h0h[off] = hi;
                g_h0l[off] = lo;
            }
        }
        __syncthreads();

        #pragma unroll
        for (int b = 0; b < 4; b++) gxv[b] = gxn[b];
    }

    if (LAYER == 1)
        g_hT[(size_t)(chunk * 4 + bb) * 256 + dir * 128 + jj] = h_last;
}

// ---------------------------------------------------------------------------
// FC head
// ---------------------------------------------------------------------------
__global__ __launch_bounds__(128)
void fc_kernel(const float* __restrict__ fc1w, const float* __restrict__ fc1b,
               const float* __restrict__ fc2w, const float* __restrict__ fc2b,
               float* __restrict__ out)
{
    __shared__ float xs[256];
    __shared__ float red[4];
    const int b = blockIdx.x, tid = threadIdx.x;
    xs[tid]       = g_hT[(size_t)b * 256 + tid];
    xs[tid + 128] = g_hT[(size_t)b * 256 + 128 + tid];
    __syncthreads();

    float s = fc1b[tid];
    const float* wr = &fc1w[(size_t)tid * 256];
    #pragma unroll 8
    for (int k = 0; k < 256; k++) s += xs[k] * wr[k];
    float a = fmaxf(s, 0.0f);

    for (int o = 0; o < 2; o++) {
        float v = a * fc2w[o * 128 + tid];
        #pragma unroll
        for (int off = 16; off > 0; off >>= 1)
            v += __shfl_xor_sync(0xffffffffu, v, off);
        if ((tid & 31) == 0) red[tid >> 5] = v;
        __syncthreads();
        if (tid == 0)
            out[b * 2 + o] = red[0] + red[1] + red[2] + red[3] + fc2b[o];
        __syncthreads();
    }
}

// ---------------------------------------------------------------------------
// Launcher (graph-capturable: kernel launches only, default stream)
// ---------------------------------------------------------------------------
extern "C" void kernel_launch(void* const* d_in, const int* in_sizes, int n_in,
                              void* d_out, int out_size)
{
    const int*   tokens = (const int*)  d_in[0];
    const float* emb    = (const float*)d_in[1];
    const float* w_ih0  = (const float*)d_in[2];   // flat [1024,300]
    const float* w_hh0  = (const float*)d_in[3];
    const float* b0     = (const float*)d_in[4];   // flat [1024]
    const float* w_ih1  = (const float*)d_in[5];   // flat [1024,256]
    const float* w_hh1  = (const float*)d_in[6];
    const float* b1     = (const float*)d_in[7];
    const float* fc1w   = (const float*)d_in[8];
    const float* fc1b   = (const float*)d_in[9];
    const float* fc2w   = (const float*)d_in[10];
    const float* fc2b   = (const float*)d_in[11];
    float* out = (float*)d_out;

    static int configured = 0;
    if (!configured) {
        cudaFuncSetAttribute((const void*)recur_kernel<0>,
                             cudaFuncAttributeMaxDynamicSharedMemorySize, REC_SMEM_BYTES);
        cudaFuncSetAttribute((const void*)recur_kernel<1>,
                             cudaFuncAttributeMaxDynamicSharedMemorySize, REC_SMEM_BYTES);
        cudaFuncSetAttribute((const void*)gemm_cp<0>,
                             cudaFuncAttributeMaxDynamicSharedMemorySize, GEMM_DSM);
        cudaFuncSetAttribute((const void*)gemm_cp<1>,
                             cudaFuncAttributeMaxDynamicSharedMemorySize, GEMM_DSM);
        configured = 1;
    }

    // 0) presplit fp32 operands into padded bf16 hi/lo (once per launch)
    presplit<0><<<(VROWS * (KP0 / 4)) / 256, 256>>>(emb,   VV, EE,  VROWS * (KP0 / 4));
    presplit<1><<<(NG    * (KP0 / 4)) / 256, 256>>>(w_ih0, NG, EE,  NG * (KP0 / 4));
    presplit<2><<<(NG    * (KP1 / 4)) / 256, 256>>>(w_ih1, NG, 256, NG * (KP1 / 4));

    // 1) Projected vocab table: P = emb @ w_ih0^T + b0   [50000,1024]
    {
        dim3 grid(NG / 128, VROWS / 128);   // (8, 391)
        gemm_cp<0><<<grid, 256, GEMM_DSM>>>(b0, VV);
    }
    // 2) Layer-0 bidirectional recurrence (gx gathered from P)
    {
        dim3 grid(64, 2);
        recur_kernel<0><<<grid, 512, REC_SMEM_BYTES>>>(tokens, w_hh0);
    }
    // 3) Layer-1 input projections: gx1 = h0_seq @ w_ih1^T + b1  [131072,1024]
    {
        dim3 grid(NG / 128, (SS * BB) / 128);    // (8, 1024)
        gemm_cp<1><<<grid, 256, GEMM_DSM>>>(b1, SS * BB);
    }
    // 4) Layer-1 bidirectional recurrence -> final hidden states
    {
        dim3 grid(64, 2);
        recur_kernel<1><<<grid, 512, REC_SMEM_BYTES>>>(tokens, w_hh1);
    }
    // 5) MLP head
    fc_kernel<<<BB, 128>>>(fc1w, fc1b, fc2w, fc2b, out);
}

// round 16
// speedup vs baseline: 1.0103x; 1.0103x over previous
#include <cuda_runtime.h>
#include <cuda_bf16.h>
#include <cstdint>
#include <cstddef>

// Problem constants
#define BB   256     // batch
#define SS   512     // seq len
#define VV   50000   // vocab
#define EE   300     // embed dim
#define HH   128     // hidden
#define NG   1024    // 2 dirs * 4H gate columns

#define VROWS 50048  // VV padded to 128
#define KP0   320    // EE padded to 32
#define KP1   256    // 2H (already /32)

// ---------------------------------------------------------------------------
// Scratch (static device globals — no runtime allocation allowed)
// ---------------------------------------------------------------------------
__device__ __align__(16) float g_P  [(size_t)VV * NG];          // projected vocab table (+b0)
__device__ __align__(16) __nv_bfloat16 g_h0h[(size_t)SS * BB * 256]; // layer-0 h, bf16 hi
__device__ __align__(16) __nv_bfloat16 g_h0l[(size_t)SS * BB * 256]; // layer-0 h, bf16 lo
__device__ __align__(16) float g_gx1[(size_t)SS * BB * NG];     // layer-1 input proj (+b1)
__device__ __align__(16) float g_hT [(size_t)BB * 256];         // layer-1 final hidden
// pre-split bf16 hi/lo operands (zero-padded) for the GEMMs
__device__ __align__(16) __nv_bfloat16 g_embh[(size_t)VROWS * KP0];
__device__ __align__(16) __nv_bfloat16 g_embl[(size_t)VROWS * KP0];
__device__ __align__(16) __nv_bfloat16 g_w0h [(size_t)NG * KP0];
__device__ __align__(16) __nv_bfloat16 g_w0l [(size_t)NG * KP0];
__device__ __align__(16) __nv_bfloat16 g_w1h [(size_t)NG * KP1];
__device__ __align__(16) __nv_bfloat16 g_w1l [(size_t)NG * KP1];

// ---------------------------------------------------------------------------
// Helpers
// ---------------------------------------------------------------------------
__device__ __forceinline__ uint32_t smem_u32(const void* p) {
    uint32_t a;
    asm("{ .reg .u64 t; cvta.to.shared.u64 t, %1; cvt.u32.u64 %0, t; }"
        : "=r"(a) : "l"(p));
    return a;
}
__device__ __forceinline__ void ffma2(unsigned long long& c,
                                      unsigned long long a,
                                      unsigned long long b) {
    asm("fma.rn.f32x2 %0, %1, %2, %0;" : "+l"(c) : "l"(a), "l"(b));
}
__device__ __forceinline__ float2 unpk2(unsigned long long v) {
    float2 f;
    asm("mov.b64 {%0, %1}, %2;" : "=f"(f.x), "=f"(f.y) : "l"(v));
    return f;
}
__device__ __forceinline__ float sigm_f(float x) {
    return 1.0f / (1.0f + __expf(-x));
}
__device__ __forceinline__ float tanh_f(float x) {
    float a = fabsf(x);
    float t = __expf(-2.0f * a);
    float r = (1.0f - t) / (1.0f + t);
    return copysignf(r, x);
}

// ldmatrix x4 (b16) — baseline PTX, legal on compute_103
__device__ __forceinline__ void ldm4(uint32_t& r0, uint32_t& r1,
                                     uint32_t& r2, uint32_t& r3, uint32_t addr) {
    asm volatile("ldmatrix.sync.aligned.m8n8.x4.shared.b16 {%0,%1,%2,%3}, [%4];"
                 : "=r"(r0), "=r"(r1), "=r"(r2), "=r"(r3) : "r"(addr));
}
// mma m16n8k16 bf16 -> f32 accumulate — baseline PTX (sm_80+)
__device__ __forceinline__ void mma16816(float* d, const uint32_t* a,
                                         uint32_t b0, uint32_t b1) {
    asm volatile(
        "mma.sync.aligned.m16n8k16.row.col.f32.bf16.bf16.f32 "
        "{%0,%1,%2,%3}, {%4,%5,%6,%7}, {%8,%9}, {%0,%1,%2,%3};"
        : "+f"(d[0]), "+f"(d[1]), "+f"(d[2]), "+f"(d[3])
        : "r"(a[0]), "r"(a[1]), "r"(a[2]), "r"(a[3]), "r"(b0), "r"(b1));
}
// cp.async 16B — baseline PTX (sm_80+)
__device__ __forceinline__ void cpa16(uint32_t dst, const void* src) {
    asm volatile("cp.async.cg.shared.global [%0], [%1], 16;" :: "r"(dst), "l"(src));
}
__device__ __forceinline__ void cp_commit() {
    asm volatile("cp.async.commit_group;" ::: "memory");
}
__device__ __forceinline__ void cp_wait0() {
    asm volatile("cp.async.wait_group 0;" ::: "memory");
}

// ---------------------------------------------------------------------------
// Presplit: fp32 [rows_src, K] -> bf16 hi/lo [*, KP] zero-padded.
// hi = rn(v), lo = rn(v - hi): identical numerics to the inline split.
// ---------------------------------------------------------------------------
template<int DST>   // 0: emb (KP0); 1: w_ih0 (KP0); 2: w_ih1 (KP1)
__global__ __launch_bounds__(256)
void presplit(const float* __restrict__ src, int rows_src, int K, int n4)
{
    __nv_bfloat16* dh = (DST == 0) ? g_embh : (DST == 1) ? g_w0h : g_w1h;
    __nv_bfloat16* dl = (DST == 0) ? g_embl : (DST == 1) ? g_w0l : g_w1l;
    const int KP = (DST == 2) ? KP1 : KP0;

    int idx = blockIdx.x * 256 + threadIdx.x;
    if (idx >= n4) return;
    int row = idx / (KP >> 2);
    int c   = (idx - row * (KP >> 2)) << 2;

    float4 v = make_float4(0.f, 0.f, 0.f, 0.f);
    if (row < rows_src && c + 3 < K)
        v = *reinterpret_cast<const float4*>(&src[(size_t)row * K + c]);

    __nv_bfloat16 hx = __float2bfloat16(v.x), hy = __float2bfloat16(v.y);
    __nv_bfloat16 hz = __float2bfloat16(v.z), hw = __float2bfloat16(v.w);
    __nv_bfloat16 lx = __float2bfloat16(v.x - __bfloat162float(hx));
    __nv_bfloat16 ly = __float2bfloat16(v.y - __bfloat162float(hy));
    __nv_bfloat16 lz = __float2bfloat16(v.z - __bfloat162float(hz));
    __nv_bfloat16 lw = __float2bfloat16(v.w - __bfloat162float(hw));

    union { __nv_bfloat162 h[2]; uint2 u; } t;
    t.h[0] = __halves2bfloat162(hx, hy); t.h[1] = __halves2bfloat162(hz, hw);
    *reinterpret_cast<uint2*>(&dh[(size_t)row * KP + c]) = t.u;
    t.h[0] = __halves2bfloat162(lx, ly); t.h[1] = __halves2bfloat162(lz, lw);
    *reinterpret_cast<uint2*>(&dl[(size_t)row * KP + c]) = t.u;
}

// ---------------------------------------------------------------------------
// Tensor-core GEMM, split-bf16 fp32 emulation (acc += AhBh + AhBl + AlBh).
// ROUND-15 FIX: kernel was latency-bound (tensor 55%, nothing saturated) —
// each emulation pass issued only 4 independent HMMAs before an accumulator
// reuse. Now pass-major across ALL FOUR np tiles: load B fragments for the
// whole 64-wide n strip, then issue 16 fully-independent HMMAs per pass
// (Bh pass, Bl pass, Bh reloaded for the Al pass). +4 ldm4/ks on B (cheap);
// per-accumulator pass & k order identical to the round-14 best -> identical
// numerics (rel_err 1.02602e-06). ks skew from round 15 reverted (regressed).
// BM=128, BN=128, BK=32, 256 threads = 8 warps (4m x 2n), warp tile 32x64.
// ---------------------------------------------------------------------------
#define GEMM_DSM 81920   // 2 * 40960 bytes

template<int WHICH>
__global__ __launch_bounds__(256, 2)
void gemm_cp(const float* __restrict__ bias, int M)
{
    extern __shared__ __align__(16) char dsm[];

    const __nv_bfloat16* __restrict__ Ah_ = (WHICH == 0) ? g_embh : g_h0h;
    const __nv_bfloat16* __restrict__ Al_ = (WHICH == 0) ? g_embl : g_h0l;
    const __nv_bfloat16* __restrict__ Bh_ = (WHICH == 0) ? g_w0h  : g_w1h;
    const __nv_bfloat16* __restrict__ Bl_ = (WHICH == 0) ? g_w0l  : g_w1l;
    float* __restrict__ C = (WHICH == 0) ? g_P : g_gx1;
    constexpr int KP  = (WHICH == 0) ? KP0 : KP1;
    constexpr int nKT = KP / 32;

    const int tid  = threadIdx.x;
    const int wid  = tid >> 5;
    const int lane = tid & 31;
    const int wm   = wid & 3;
    const int wn   = wid >> 2;

    const int mTile = blockIdx.y * 128;
    const int nTile = blockIdx.x * 128;
    const uint32_t sb = smem_u32(dsm);

    // fill geometry: thread -> row fr, 2x16B at col half fc
    const int fr = tid >> 1;
    const int fc = (tid & 1) * 16;                 // bf16 elems
    const __nv_bfloat16* sAh = Ah_ + (size_t)(mTile + fr) * KP + fc;
    const __nv_bfloat16* sAl = Al_ + (size_t)(mTile + fr) * KP + fc;
    const __nv_bfloat16* sBh = Bh_ + (size_t)(nTile + fr) * KP + fc;
    const __nv_bfloat16* sBl = Bl_ + (size_t)(nTile + fr) * KP + fc;
    const uint32_t dstb = (uint32_t)(fr * 80 + fc * 2);   // bytes in matrix region

    // ldmatrix lane geometry (m16n8k16 fragments)
    const int a_row = ((lane >> 3) & 1) * 8 + (lane & 7);
    const int a_k   = (lane >> 4) * 8;
    const int b_row = (lane >> 4) * 8 + (lane & 7);
    const int b_k   = ((lane >> 3) & 1) * 8;

    float acc[2][8][4];
    #pragma unroll
    for (int i = 0; i < 2; i++)
        #pragma unroll
        for (int j = 0; j < 8; j++)
            #pragma unroll
            for (int q = 0; q < 4; q++) acc[i][j][q] = 0.0f;

    // prologue: tile 0 -> buffer 0
    {
        const uint32_t d = sb + dstb;
        cpa16(d,             sAh);  cpa16(d + 16,         sAh + 8);
        cpa16(d + 10240,     sAl);  cpa16(d + 10240 + 16, sAl + 8);
        cpa16(d + 20480,     sBh);  cpa16(d + 20480 + 16, sBh + 8);
        cpa16(d + 30720,     sBl);  cpa16(d + 30720 + 16, sBl + 8);
        cp_commit();
    }

    for (int kt = 0; kt < nKT; kt++) {
        cp_wait0();          // tile kt landed (only group pending)
        __syncthreads();     // all warps: kt visible; compute(kt-1) complete

        // issue next tile AFTER the barrier -> overlaps with compute below
        if (kt + 1 < nKT) {
            const uint32_t d = sb + (uint32_t)(((kt + 1) & 1) * 40960) + dstb;
            const int ko = (kt + 1) * 32;
            cpa16(d,             sAh + ko);  cpa16(d + 16,         sAh + ko + 8);
            cpa16(d + 10240,     sAl + ko);  cpa16(d + 10240 + 16, sAl + ko + 8);
            cpa16(d + 20480,     sBh + ko);  cpa16(d + 20480 + 16, sBh + ko + 8);
            cpa16(d + 30720,     sBl + ko);  cpa16(d + 30720 + 16, sBl + ko + 8);
            cp_commit();
        }

        const uint32_t uAh = sb + (uint32_t)((kt & 1) * 40960);
        const uint32_t uAl = uAh + 10240;
        const uint32_t uBh = uAh + 20480;
        const uint32_t uBl = uAh + 30720;

        #pragma unroll
        for (int ks = 0; ks < 2; ks++) {
            uint32_t ah[2][4], al[2][4];
            #pragma unroll
            for (int mt = 0; mt < 2; mt++) {
                const uint32_t off =
                    (uint32_t)(((wm * 32 + mt * 16 + a_row) * 40 + ks * 16 + a_k) * 2);
                ldm4(ah[mt][0], ah[mt][1], ah[mt][2], ah[mt][3], uAh + off);
                ldm4(al[mt][0], al[mt][1], al[mt][2], al[mt][3], uAl + off);
            }
            uint32_t boffs[4];
            #pragma unroll
            for (int np = 0; np < 4; np++)
                boffs[np] = (uint32_t)(((wn * 64 + np * 16 + b_row) * 40
                                        + ks * 16 + b_k) * 2);
            uint32_t bfr[4][4];

            // pass 0: Ah x Bh — 16 independent HMMAs
            #pragma unroll
            for (int np = 0; np < 4; np++)
                ldm4(bfr[np][0], bfr[np][1], bfr[np][2], bfr[np][3], uBh + boffs[np]);
            #pragma unroll
            for (int np = 0; np < 4; np++) {
                #pragma unroll
                for (int h2 = 0; h2 < 2; h2++) {
                    mma16816(acc[0][np * 2 + h2], ah[0], bfr[np][2*h2], bfr[np][2*h2+1]);
                    mma16816(acc[1][np * 2 + h2], ah[1], bfr[np][2*h2], bfr[np][2*h2+1]);
                }
            }
            // pass 1: Ah x Bl — 16 independent HMMAs
            #pragma unroll
            for (int np = 0; np < 4; np++)
                ldm4(bfr[np][0], bfr[np][1], bfr[np][2], bfr[np][3], uBl + boffs[np]);
            #pragma unroll
            for (int np = 0; np < 4; np++) {
                #pragma unroll
                for (int h2 = 0; h2 < 2; h2++) {
                    mma16816(acc[0][np * 2 + h2], ah[0], bfr[np][2*h2], bfr[np][2*h2+1]);
                    mma16816(acc[1][np * 2 + h2], ah[1], bfr[np][2*h2], bfr[np][2*h2+1]);
                }
            }
            // pass 2: Al x Bh — 16 independent HMMAs (Bh reloaded)
            #pragma unroll
            for (int np = 0; np < 4; np++)
                ldm4(bfr[np][0], bfr[np][1], bfr[np][2], bfr[np][3], uBh + boffs[np]);
            #pragma unroll
            for (int np = 0; np < 4; np++) {
                #pragma unroll
                for (int h2 = 0; h2 < 2; h2++) {
                    mma16816(acc[0][np * 2 + h2], al[0], bfr[np][2*h2], bfr[np][2*h2+1]);
                    mma16816(acc[1][np * 2 + h2], al[1], bfr[np][2*h2], bfr[np][2*h2+1]);
                }
            }
        }
    }

    // ---- epilogue: c-frag rows lane>>2 (+8), cols (lane&3)*2; guard M
    const int lrow = lane >> 2;
    const int lcol = (lane & 3) * 2;
    #pragma unroll
    for (int mt = 0; mt < 2; mt++) {
        const int gm0 = mTile + wm * 32 + mt * 16 + lrow;
        #pragma unroll
        for (int nt = 0; nt < 8; nt++) {
            const int gn0 = nTile + wn * 64 + nt * 8 + lcol;
            const float bz0 = bias[gn0], bz1 = bias[gn0 + 1];
            if (gm0 < M) {
                float2 v = make_float2(acc[mt][nt][0] + bz0, acc[mt][nt][1] + bz1);
                *reinterpret_cast<float2*>(&C[(size_t)gm0 * NG + gn0]) = v;
            }
            if (gm0 + 8 < M) {
                float2 v = make_float2(acc[mt][nt][2] + bz0, acc[mt][nt][3] + bz1);
                *reinterpret_cast<float2*>(&C[(size_t)(gm0 + 8) * NG + gn0]) = v;
            }
        }
    }
}

// ---------------------------------------------------------------------------
// Recurrence v5 (measured best — UNCHANGED).
// G=2 gates per thread, k-split 2; g0 w-half in regs, g1 w-half in smem slots;
// h_sm 72-float half-pitch; kh-pair shfl_xor(1); transposed z_sm[b][520];
// gx prefetched one step ahead.
// LAYER==0 emits h as bf16 hi/lo (pre-split for GEMM1's A operand).
// ---------------------------------------------------------------------------
#define REC_SMEM_BYTES ((32768 + 576 + 2080) * 4 + 2048 * 4)

template<int LAYER>
__global__ __launch_bounds__(512, 1)
void recur_kernel(const int* __restrict__ tokens,
                  const float* __restrict__ w_hh)   // [2,512,128]
{
    extern __shared__ __align__(16) float smem[];
    float* w_sm   = smem;                    // slot layout, 32768 floats
    float* h_sm   = smem + 32768;            // [4 b][2 kh x 72]
    float* z_sm   = h_sm + 576;              // [4 b][520]
    int*   tok_sm = (int*)(z_sm + 2080);     // [4][512]

    const int tid   = threadIdx.x;
    const int chunk = blockIdx.x;
    const int dir   = blockIdx.y;
    const int gp    = tid >> 1;
    const int kh    = tid & 1;
    const int warp  = tid >> 5;
    const int lane  = tid & 31;

    unsigned long long wr2[32];
    {
        const unsigned long long* wp = reinterpret_cast<const unsigned long long*>(
            &w_hh[((size_t)dir * 512 + 2 * gp) * 128 + kh * 64]);
        #pragma unroll
        for (int i = 0; i < 32; i++) wr2[i] = wp[i];
    }
    {
        const float* wsrc = &w_hh[((size_t)dir * 512 + 2 * gp + 1) * 128 + kh * 64];
        float* wdst = &w_sm[(size_t)(warp * 16 * 32 + lane) * 4];
        #pragma unroll
        for (int t = 0; t < 16; t++)
            *reinterpret_cast<float4*>(&wdst[t * 128]) =
                *reinterpret_cast<const float4*>(&wsrc[t * 4]);
    }
    if (LAYER == 0) {
        for (int idx = tid; idx < 4 * 512; idx += 512)
            tok_sm[idx] = tokens[(size_t)(chunk * 4 + (idx >> 9)) * SS + (idx & 511)];
    }
    for (int idx = tid; idx < 576; idx += 512) h_sm[idx] = 0.0f;
    __syncthreads();

    const int jj = tid & 127;
    const int bb = tid >> 7;
    const int col = dir * 512 + tid;
    const float* __restrict__ gsrc = (LAYER == 0) ? g_P : g_gx1;
    const float* wslot = &w_sm[(size_t)(warp * 16 * 32 + lane) * 4];
    float c_st = 0.0f, h_last = 0.0f;

    // prologue: gx for step 0
    float gxv[4];
    {
        const int s0 = dir ? 511 : 0;
        #pragma unroll
        for (int b = 0; b < 4; b++) {
            size_t row = (LAYER == 0)
                ? (size_t)tok_sm[b * 512 + s0]
                : ((size_t)s0 * BB + (chunk * 4 + b));
            gxv[b] = gsrc[row * NG + col];
        }
    }

    for (int si = 0; si < 512; si++) {
        const int s = dir ? (511 - si) : si;

        // --- prefetch gx for step si+1 (consumed next iter; DRAM hidden)
        float gxn[4] = {0.f, 0.f, 0.f, 0.f};
        if (si < 511) {
            const int sn = dir ? (510 - si) : (si + 1);
            #pragma unroll
            for (int b = 0; b < 4; b++) {
                size_t row = (LAYER == 0)
                    ? (size_t)tok_sm[b * 512 + sn]
                    : ((size_t)sn * BB + (chunk * 4 + b));
                gxn[b] = gsrc[row * NG + col];
            }
        }

        unsigned long long accA[4] = {0ull, 0ull, 0ull, 0ull};
        unsigned long long accB[4] = {0ull, 0ull, 0ull, 0ull};
        #pragma unroll
        for (int t = 0; t < 16; t++) {
            ulonglong2 w2 = *reinterpret_cast<const ulonglong2*>(&wslot[t * 128]);
            #pragma unroll
            for (int b = 0; b < 4; b++) {
                ulonglong2 h2 = *reinterpret_cast<const ulonglong2*>(
                    &h_sm[b * 144 + kh * 72 + t * 4]);
                ffma2(accA[b], wr2[2 * t],     h2.x);
                ffma2(accA[b], wr2[2 * t + 1], h2.y);
                ffma2(accB[b], w2.x, h2.x);
                ffma2(accB[b], w2.y, h2.y);
            }
        }
        #pragma unroll
        for (int b = 0; b < 4; b++) {
            float2 fA = unpk2(accA[b]);
            float2 fB = unpk2(accB[b]);
            float sA = fA.x + fA.y;
            float sB = fB.x + fB.y;
            float send = kh ? sA : sB;
            float recv = __shfl_xor_sync(0xffffffffu, send, 1);
            float own  = kh ? sB : sA;
            z_sm[b * 520 + tid] = own + recv + gxv[b];
        }
        __syncthreads();

        {
            const float* zrow = &z_sm[bb * 520];
            float zi = zrow[      jj];
            float zf = zrow[128 + jj];
            float zg = zrow[256 + jj];
            float zo = zrow[384 + jj];
            float ig = sigm_f(zi), fg = sigm_f(zf), og = sigm_f(zo);
            float gv = tanh_f(zg);
            c_st = fg * c_st + ig * gv;
            float hh = og * tanh_f(c_st);
            h_last = hh;
            h_sm[bb * 144 + (jj >> 6) * 72 + (jj & 63)] = hh;
            if (LAYER == 0) {
                __nv_bfloat16 hi = __float2bfloat16(hh);
                __nv_bfloat16 lo = __float2bfloat16(hh - __bfloat162float(hi));
                const size_t off =
                    ((size_t)s * BB + (chunk * 4 + bb)) * 256 + dir * 128 + jj;
                g_h0h[off] = hi;
                g_h0l[off] = lo;
            }
        }
        __syncthreads();

        #pragma unroll
        for (int b = 0; b < 4; b++) gxv[b] = gxn[b];
    }

    if (LAYER == 1)
        g_hT[(size_t)(chunk * 4 + bb) * 256 + dir * 128 + jj] = h_last;
}

// ---------------------------------------------------------------------------
// FC head
// ---------------------------------------------------------------------------
__global__ __launch_bounds__(128)
void fc_kernel(const float* __restrict__ fc1w, const float* __restrict__ fc1b,
               const float* __restrict__ fc2w, const float* __restrict__ fc2b,
               float* __restrict__ out)
{
    __shared__ float xs[256];
    __shared__ float red[4];
    const int b = blockIdx.x, tid = threadIdx.x;
    xs[tid]       = g_hT[(size_t)b * 256 + tid];
    xs[tid + 128] = g_hT[(size_t)b * 256 + 128 + tid];
    __syncthreads();

    float s = fc1b[tid];
    const float* wr = &fc1w[(size_t)tid * 256];
    #pragma unroll 8
    for (int k = 0; k < 256; k++) s += xs[k] * wr[k];
    float a = fmaxf(s, 0.0f);

    for (int o = 0; o < 2; o++) {
        float v = a * fc2w[o * 128 + tid];
        #pragma unroll
        for (int off = 16; off > 0; off >>= 1)
            v += __shfl_xor_sync(0xffffffffu, v, off);
        if ((tid & 31) == 0) red[tid >> 5] = v;
        __syncthreads();
        if (tid == 0)
            out[b * 2 + o] = red[0] + red[1] + red[2] + red[3] + fc2b[o];
        __syncthreads();
    }
}

// ---------------------------------------------------------------------------
// Launcher (graph-capturable: kernel launches only, default stream)
// ---------------------------------------------------------------------------
extern "C" void kernel_launch(void* const* d_in, const int* in_sizes, int n_in,
                              void* d_out, int out_size)
{
    const int*   tokens = (const int*)  d_in[0];
    const float* emb    = (const float*)d_in[1];
    const float* w_ih0  = (const float*)d_in[2];   // flat [1024,300]
    const float* w_hh0  = (const float*)d_in[3];
    const float* b0     = (const float*)d_in[4];   // flat [1024]
    const float* w_ih1  = (const float*)d_in[5];   // flat [1024,256]
    const float* w_hh1  = (const float*)d_in[6];
    const float* b1     = (const float*)d_in[7];
    const float* fc1w   = (const float*)d_in[8];
    const float* fc1b   = (const float*)d_in[9];
    const float* fc2w   = (const float*)d_in[10];
    const float* fc2b   = (const float*)d_in[11];
    float* out = (float*)d_out;

    static int configured = 0;
    if (!configured) {
        cudaFuncSetAttribute((const void*)recur_kernel<0>,
                             cudaFuncAttributeMaxDynamicSharedMemorySize, REC_SMEM_BYTES);
        cudaFuncSetAttribute((const void*)recur_kernel<1>,
                             cudaFuncAttributeMaxDynamicSharedMemorySize, REC_SMEM_BYTES);
        cudaFuncSetAttribute((const void*)gemm_cp<0>,
                             cudaFuncAttributeMaxDynamicSharedMemorySize, GEMM_DSM);
        cudaFuncSetAttribute((const void*)gemm_cp<1>,
                             cudaFuncAttributeMaxDynamicSharedMemorySize, GEMM_DSM);
        configured = 1;
    }

    // 0) presplit fp32 operands into padded bf16 hi/lo (once per launch)
    presplit<0><<<(VROWS * (KP0 / 4)) / 256, 256>>>(emb,   VV, EE,  VROWS * (KP0 / 4));
    presplit<1><<<(NG    * (KP0 / 4)) / 256, 256>>>(w_ih0, NG, EE,  NG * (KP0 / 4));
    presplit<2><<<(NG    * (KP1 / 4)) / 256, 256>>>(w_ih1, NG, 256, NG * (KP1 / 4));

    // 1) Projected vocab table: P = emb @ w_ih0^T + b0   [50000,1024]
    {
        dim3 grid(NG / 128, VROWS / 128);   // (8, 391)
        gemm_cp<0><<<grid, 256, GEMM_DSM>>>(b0, VV);
    }
    // 2) Layer-0 bidirectional recurrence (gx gathered from P)
    {
        dim3 grid(64, 2);
        recur_kernel<0><<<grid, 512, REC_SMEM_BYTES>>>(tokens, w_hh0);
    }
    // 3) Layer-1 input projections: gx1 = h0_seq @ w_ih1^T + b1  [131072,1024]
    {
        dim3 grid(NG / 128, (SS * BB) / 128);    // (8, 1024)
        gemm_cp<1><<<grid, 256, GEMM_DSM>>>(b1, SS * BB);
    }
    // 4) Layer-1 bidirectional recurrence -> final hidden states
    {
        dim3 grid(64, 2);
        recur_kernel<1><<<grid, 512, REC_SMEM_BYTES>>>(tokens, w_hh1);
    }
    // 5) MLP head
    fc_kernel<<<BB, 128>>>(fc1w, fc1b, fc2w, fc2b, out);
}